// round 14
// baseline (speedup 1.0000x reference)
#include <cuda_runtime.h>
#include <cuda_bf16.h>
#include <cuda_fp16.h>
#include <cstdint>

#define NN 50000
#define EE 600000
#define HH 128
#define GG 2048
#define NBLK2 196        // ceil(50000/256)
#define MBLK 782         // ceil(50000/64)
#define KPAD 136         // padded row length (conflict-free ldmatrix rows)

// ---------------- scratch (static device globals) ----------------
__device__ __half g_h16[NN * HH];   // GEMM output (fp16, gather operand)
__device__ float g_agg[NN * HH];    // conv output (pre-BN, fp32)
__device__ float g_xagg[NN * 9];    // aggregated raw features (layer-0 trick)
__device__ float g_dis[NN];         // deg^-1/2 (incl self loop)
__device__ int   g_deg[NN];
__device__ int   g_rowstart[NN + 1];
__device__ int   g_cursor[NN];
__device__ int2  g_edge[EE];        // (src, coef-bits) per CSR slot
__device__ int   g_partial[256];
__device__ float g_sumL[3][HH];
__device__ float g_sumsqL[3][HH];
__device__ int   g_gstart[GG], g_gend[GG];
__device__ __half g_Wimg[2][128 * KPAD];  // [layer] fp16 W^T padded [n][k]

// ---------------- fused preprocessing: zero deg/xagg/stats + W images + ranges ----------------
__global__ __launch_bounds__(512) void k_init(const int* __restrict__ batch,
                                              const float* __restrict__ W1,
                                              const float* __restrict__ W2) {
    int i = blockIdx.x * blockDim.x + threadIdx.x;   // 0 .. 50175
    const int gstride = 98 * 512;                     // 50176
    if (i < NN) {
        g_deg[i] = 0;
        int b = batch[i];
        if (i == 0 || batch[i - 1] != b) g_gstart[b] = i;
        if (i == NN - 1 || batch[i + 1] != b) g_gend[b] = i + 1;
    }
    // zero g_xagg (450000 floats)
    for (int j = i; j < NN * 9; j += gstride) g_xagg[j] = 0.f;
    if (i < 3 * HH) { ((float*)g_sumL)[i] = 0.f; ((float*)g_sumsqL)[i] = 0.f; }
    if (i == 0) g_rowstart[NN] = EE;
    // W images: 2*128*128 = 32768 elements
    if (i < 2 * 128 * 128) {
        int mat = i >> 14;
        int rem = i & 16383;
        int n = rem >> 7;
        int k = rem & 127;
        float v = (mat ? W2 : W1)[k * 128 + n];
        g_Wimg[mat][n * KPAD + k] = __float2half_rn(v);
    }
}

__global__ void k_deg(const int* __restrict__ dst) {
    int e = blockIdx.x * blockDim.x + threadIdx.x;
    if (e < EE) atomicAdd(&g_deg[dst[e]], 1);
}

__global__ __launch_bounds__(256) void k_blocksum() {
    int t = threadIdx.x;
    int i = blockIdx.x * 256 + t;
    int v = (i < NN) ? g_deg[i] : 0;
    if (i < NN) g_dis[i] = rsqrtf((float)v + 1.0f);
    int s = v;
#pragma unroll
    for (int o = 16; o > 0; o >>= 1) s += __shfl_down_sync(0xffffffffu, s, o);
    __shared__ int ws[8];
    if ((t & 31) == 0) ws[t >> 5] = s;
    __syncthreads();
    if (t < 8) {
        int x = ws[t];
#pragma unroll
        for (int o = 4; o > 0; o >>= 1) x += __shfl_down_sync(0xffu, x, o);
        if (t == 0) g_partial[blockIdx.x] = x;
    }
}

// merged: each block scans the 196 partials itself, then does its local scan
__global__ __launch_bounds__(256) void k_scanlocal() {
    __shared__ int pp[256];
    __shared__ int blockoff;
    int t = threadIdx.x;
    int lane = t & 31, w = t >> 5;

    // phase A: scan partials to get this block's exclusive offset
    int pv = (t < NBLK2) ? g_partial[t] : 0;
    pp[t] = pv;
    __syncthreads();
    for (int o = 1; o < 256; o <<= 1) {
        int xx = (t >= o) ? pp[t - o] : 0;
        __syncthreads();
        pp[t] += xx;
        __syncthreads();
    }
    if (t == blockIdx.x) blockoff = pp[t] - pv;   // blockIdx.x < 196 < 256
    __syncthreads();

    // phase B: local exclusive scan
    int i = blockIdx.x * 256 + t;
    int v = (i < NN) ? g_deg[i] : 0;
    int x = v;
#pragma unroll
    for (int o = 1; o < 32; o <<= 1) {
        int y = __shfl_up_sync(0xffffffffu, x, o);
        if (lane >= o) x += y;
    }
    __shared__ int ws[8];
    if (lane == 31) ws[w] = x;
    __syncthreads();
    int add = blockoff;
    for (int j = 0; j < 8; j++) add += (j < w) ? ws[j] : 0;
    int excl = x - v + add;
    if (i < NN) { g_rowstart[i] = excl; g_cursor[i] = excl; }
}

// fill CSR + fused layer-0 raw-feature scatter (9 channels, fp32 atomics)
__global__ void k_fill(const int* __restrict__ src, const int* __restrict__ dst,
                       const float* __restrict__ x) {
    int e = blockIdx.x * blockDim.x + threadIdx.x;
    if (e >= EE) return;
    int d = dst[e], s = src[e];
    int p = atomicAdd(&g_cursor[d], 1);
    float c = g_dis[s] * g_dis[d];
    g_edge[p] = make_int2(s, __float_as_int(c));
    const float* xs = &x[s * 9];
    float* xa = &g_xagg[d * 9];
#pragma unroll
    for (int j = 0; j < 9; j++) atomicAdd(&xa[j], xs[j] * c);
}

// ---------------- GEMM layer 0: g_agg = (xagg + x*dis^2) @ W0 + b0, fused BN stats ----------------
__global__ __launch_bounds__(256) void k_gemm0(const float* __restrict__ W0,
                                               const float* __restrict__ b0,
                                               const float* __restrict__ x) {
    __shared__ float Ws[9 * 128];
    __shared__ float sm[8][128];
    int tid = threadIdx.x;
    for (int i = tid; i < 9 * 128; i += 256) Ws[i] = W0[i];
    __syncthreads();
    int rsub = tid >> 5;       // 8 rows per block
    int c4 = tid & 31;
    int row = blockIdx.x * 8 + rsub;   // grid exactly covers NN
    float di = g_dis[row];
    float d2 = di * di;
    float xr[9];
#pragma unroll
    for (int k = 0; k < 9; k++) xr[k] = g_xagg[row * 9 + k] + x[row * 9 + k] * d2;
    float4 acc = ((const float4*)b0)[c4];
#pragma unroll
    for (int k = 0; k < 9; k++) {
        float4 w = *(const float4*)&Ws[k * 128 + c4 * 4];
        acc.x += xr[k] * w.x; acc.y += xr[k] * w.y;
        acc.z += xr[k] * w.z; acc.w += xr[k] * w.w;
    }
    *(float4*)&g_agg[(size_t)row * 128 + c4 * 4] = acc;

    // fused BN stats (layer-0)
    *(float4*)&sm[rsub][c4 * 4] = acc;
    __syncthreads();
    if (tid < 128) {
        float s = 0.f, q = 0.f;
#pragma unroll
        for (int j = 0; j < 8; j++) {
            float v = sm[j][tid];
            s += v;
            q += v * v;
        }
        atomicAdd(&g_sumL[0][tid], s);
        atomicAdd(&g_sumsqL[0][tid], q);
    }
}

// ---------------- GEMM layers 1,2: single-pass fp16 mma.sync + ldmatrix ----------------
#define SM_SC  0
#define SM_SH  512
#define SM_A16 1024
#define SM_B16 (1024 + 64 * KPAD * 2)
#define SM_TOT (SM_B16 + 128 * KPAD * 2)

__device__ __forceinline__ void ldm_x4(uint32_t* f, uint32_t addr) {
    asm volatile("ldmatrix.sync.aligned.m8n8.x4.shared.b16 {%0,%1,%2,%3}, [%4];"
                 : "=r"(f[0]), "=r"(f[1]), "=r"(f[2]), "=r"(f[3]) : "r"(addr));
}

__global__ __launch_bounds__(256, 2)
void k_tcgemm(const float* __restrict__ gamma, const float* __restrict__ beta,
              int sidx, int wmat) {
    extern __shared__ char smem[];
    float* sc = (float*)(smem + SM_SC);
    float* sh = (float*)(smem + SM_SH);
    __half* A16 = (__half*)(smem + SM_A16);
    __half* B16 = (__half*)(smem + SM_B16);

    int tid = threadIdx.x;
    int rbase = blockIdx.x * 64;

    if (tid < 128) {
        float m = g_sumL[sidx][tid] * (1.0f / NN);
        float v = g_sumsqL[sidx][tid] * (1.0f / NN) - m * m;
        float s = rsqrtf(v + 1e-5f) * gamma[tid];
        sc[tid] = s;
        sh[tid] = beta[tid] - m * s;
    }
    {
        const float4* bsrc = (const float4*)g_Wimg[wmat];
        float4* bd = (float4*)B16;
        for (int i = tid; i < 128 * KPAD / 8; i += 256) bd[i] = bsrc[i];
    }
    __syncthreads();

    // A tile: BN+ReLU -> fp16
#pragma unroll
    for (int it = 0; it < 8; it++) {
        int g = tid + it * 256;
        int row = g >> 5;
        int c = (g & 31) * 4;
        int grow = rbase + row;
        float4 v = {0.f, 0.f, 0.f, 0.f};
        if (grow < NN) v = *(const float4*)&g_agg[(size_t)grow * 128 + c];
        float a0 = fmaxf(v.x * sc[c + 0] + sh[c + 0], 0.f);
        float a1 = fmaxf(v.y * sc[c + 1] + sh[c + 1], 0.f);
        float a2 = fmaxf(v.z * sc[c + 2] + sh[c + 2], 0.f);
        float a3 = fmaxf(v.w * sc[c + 3] + sh[c + 3], 0.f);
        __half2* dst2 = (__half2*)&A16[row * KPAD + c];
        dst2[0] = __floats2half2_rn(a0, a1);
        dst2[1] = __floats2half2_rn(a2, a3);
    }
    __syncthreads();

    int wid = tid >> 5;
    int lane = tid & 31;
    int wm = wid & 1;
    int wn = wid >> 1;
    int quad = lane >> 3;
    int qr = lane & 7;
    int grp = lane >> 2;
    int tig = lane & 3;

    int aoff = ((quad & 1) * 8 + qr) * KPAD + (quad >> 1) * 8;
    int boff = ((quad >> 1) * 8 + qr) * KPAD + (quad & 1) * 8;

    uint32_t a_b = (uint32_t)__cvta_generic_to_shared(A16);
    uint32_t b_b = (uint32_t)__cvta_generic_to_shared(B16);

    float acc[2][4][4];
#pragma unroll
    for (int i = 0; i < 2; i++)
#pragma unroll
        for (int j = 0; j < 4; j++)
#pragma unroll
            for (int l = 0; l < 4; l++) acc[i][j][l] = 0.f;

#pragma unroll
    for (int kk = 0; kk < 8; kk++) {
        int k0 = kk * 16;
        uint32_t af[2][4], bf[2][4];
#pragma unroll
        for (int mt = 0; mt < 2; mt++)
            ldm_x4(af[mt], a_b + (uint32_t)(((wm * 32 + mt * 16) * KPAD + k0 + aoff) * 2));
#pragma unroll
        for (int g2 = 0; g2 < 2; g2++)
            ldm_x4(bf[g2], b_b + (uint32_t)(((wn * 32 + g2 * 16) * KPAD + k0 + boff) * 2));
#pragma unroll
        for (int mt = 0; mt < 2; mt++) {
#pragma unroll
            for (int nt = 0; nt < 4; nt++) {
                uint32_t b0 = bf[nt >> 1][(nt & 1) * 2];
                uint32_t b1 = bf[nt >> 1][(nt & 1) * 2 + 1];
                asm volatile(
                    "mma.sync.aligned.m16n8k16.row.col.f32.f16.f16.f32 "
                    "{%0,%1,%2,%3}, {%4,%5,%6,%7}, {%8,%9}, {%0,%1,%2,%3};"
                    : "+f"(acc[mt][nt][0]), "+f"(acc[mt][nt][1]),
                      "+f"(acc[mt][nt][2]), "+f"(acc[mt][nt][3])
                    : "r"(af[mt][0]), "r"(af[mt][1]), "r"(af[mt][2]), "r"(af[mt][3]),
                      "r"(b0), "r"(b1));
            }
        }
    }

    __half2* hv = (__half2*)g_h16;
#pragma unroll
    for (int mt = 0; mt < 2; mt++) {
        int row0 = rbase + wm * 32 + mt * 16 + grp;
        int row1 = row0 + 8;
#pragma unroll
        for (int nt = 0; nt < 4; nt++) {
            int col = wn * 32 + nt * 8 + tig * 2;
            if (row0 < NN)
                hv[row0 * 64 + (col >> 1)] = __floats2half2_rn(acc[mt][nt][0], acc[mt][nt][1]);
            if (row1 < NN)
                hv[row1 * 64 + (col >> 1)] = __floats2half2_rn(acc[mt][nt][2], acc[mt][nt][3]);
        }
    }
}

// ---------------- gather (fp16 operand, x2 unroll) + fused BN stats ----------------
__global__ __launch_bounds__(256) void k_gather(const float* __restrict__ bias, int sidx) {
    int w = threadIdx.x >> 5;
    int lane = threadIdx.x & 31;
    int node = blockIdx.x * 8 + w;
    int beg = g_rowstart[node], end = g_rowstart[node + 1];
    const uint2* hv = (const uint2*)g_h16;

    float4 a0 = {0.f, 0.f, 0.f, 0.f}, a1 = {0.f, 0.f, 0.f, 0.f};
    int e = beg;
    for (; e + 2 <= end; e += 2) {
        int2 e0 = g_edge[e], e1 = g_edge[e + 1];
        uint2 u0 = hv[(size_t)e0.x * 32 + lane];
        uint2 u1 = hv[(size_t)e1.x * 32 + lane];
        float c0 = __int_as_float(e0.y), c1 = __int_as_float(e1.y);
        float2 f00 = __half22float2(*(__half2*)&u0.x);
        float2 f01 = __half22float2(*(__half2*)&u0.y);
        float2 f10 = __half22float2(*(__half2*)&u1.x);
        float2 f11 = __half22float2(*(__half2*)&u1.y);
        a0.x += f00.x * c0; a0.y += f00.y * c0; a0.z += f01.x * c0; a0.w += f01.y * c0;
        a1.x += f10.x * c1; a1.y += f10.y * c1; a1.z += f11.x * c1; a1.w += f11.y * c1;
    }
    if (e < end) {
        int2 e0 = g_edge[e];
        uint2 u0 = hv[(size_t)e0.x * 32 + lane];
        float c0 = __int_as_float(e0.y);
        float2 f00 = __half22float2(*(__half2*)&u0.x);
        float2 f01 = __half22float2(*(__half2*)&u0.y);
        a0.x += f00.x * c0; a0.y += f00.y * c0; a0.z += f01.x * c0; a0.w += f01.y * c0;
    }
    float di = g_dis[node];
    float d2 = di * di;
    uint2 us = hv[(size_t)node * 32 + lane];
    float2 s0 = __half22float2(*(__half2*)&us.x);
    float2 s1 = __half22float2(*(__half2*)&us.y);
    float4 bb = ((const float4*)bias)[lane];
    float4 acc;
    acc.x = a0.x + a1.x + s0.x * d2 + bb.x;
    acc.y = a0.y + a1.y + s0.y * d2 + bb.y;
    acc.z = a0.z + a1.z + s1.x * d2 + bb.z;
    acc.w = a0.w + a1.w + s1.y * d2 + bb.w;
    ((float4*)g_agg)[(size_t)node * 32 + lane] = acc;

    __shared__ float sm[8][128];
    *(float4*)&sm[w][lane * 4] = acc;
    __syncthreads();
    int t = threadIdx.x;
    if (t < 128) {
        float s = 0.f, q = 0.f;
#pragma unroll
        for (int j = 0; j < 8; j++) {
            float v = sm[j][t];
            s += v;
            q += v * v;
        }
        atomicAdd(&g_sumL[sidx][t], s);
        atomicAdd(&g_sumsqL[sidx][t], q);
    }
}

// ---------------- fused pool (BN2 inline) + MLP head (per-graph, 2048 blocks) ----------------
__global__ __launch_bounds__(128) void k_poolmlp(const float* __restrict__ gamma,
                                                 const float* __restrict__ beta,
                                                 const float* __restrict__ fc1_w,
                                                 const float* __restrict__ fc1_b,
                                                 const float* __restrict__ fc2_w,
                                                 const float* __restrict__ fc2_b,
                                                 const float* __restrict__ out_w,
                                                 const float* __restrict__ out_b,
                                                 float* __restrict__ out) {
    __shared__ float zs[256];
    __shared__ float h1[128];
    __shared__ float h2[64];
    int g = blockIdx.x;
    int t = threadIdx.x;

    float m = g_sumL[2][t] * (1.0f / NN);
    float va = g_sumsqL[2][t] * (1.0f / NN) - m * m;
    float sc = rsqrtf(va + 1e-5f) * gamma[t];
    float sh = beta[t] - m * sc;

    int s = g_gstart[g], e = g_gend[g];
    float sum = 0.f, mx = -3.4e38f;
    for (int n = s; n < e; n++) {
        float v = fmaxf(g_agg[(size_t)n * 128 + t] * sc + sh, 0.f);
        sum += v;
        mx = fmaxf(mx, v);
    }
    zs[t] = sum / (float)(e - s);
    zs[128 + t] = mx;
    __syncthreads();

    float acc = fc1_b[t];
#pragma unroll 8
    for (int k = 0; k < 256; k++) acc += zs[k] * fc1_w[k * 128 + t];
    h1[t] = fmaxf(acc, 0.f);
    __syncthreads();
    if (t < 64) {
        float a = fc2_b[t];
#pragma unroll 8
        for (int k = 0; k < 128; k++) a += h1[k] * fc2_w[k * 64 + t];
        h2[t] = fmaxf(a, 0.f);
    }
    __syncthreads();
    if (t < 5) {
        float a = out_b[t];
#pragma unroll
        for (int k = 0; k < 64; k++) a += h2[k] * out_w[k * 5 + t];
        out[g * 5 + t] = a;
    }
}

// ---------------- launch ----------------
extern "C" void kernel_launch(void* const* d_in, const int* in_sizes, int n_in,
                              void* d_out, int out_size) {
    const float* x = (const float*)d_in[0];
    const int* ei = (const int*)d_in[1];
    const int* src = ei;
    const int* dst = ei + EE;
    const int* batch = (const int*)d_in[2];
    const float* W0 = (const float*)d_in[3];
    const float* b0 = (const float*)d_in[4];
    const float* gm0 = (const float*)d_in[5];
    const float* be0 = (const float*)d_in[6];
    const float* W1 = (const float*)d_in[7];
    const float* b1 = (const float*)d_in[8];
    const float* gm1 = (const float*)d_in[9];
    const float* be1 = (const float*)d_in[10];
    const float* W2 = (const float*)d_in[11];
    const float* b2 = (const float*)d_in[12];
    const float* gm2 = (const float*)d_in[13];
    const float* be2 = (const float*)d_in[14];
    const float* fc1_w = (const float*)d_in[15];
    const float* fc1_b = (const float*)d_in[16];
    const float* fc2_w = (const float*)d_in[17];
    const float* fc2_b = (const float*)d_in[18];
    const float* out_w = (const float*)d_in[19];
    const float* out_b = (const float*)d_in[20];
    float* out = (float*)d_out;

    cudaFuncSetAttribute(k_tcgemm, cudaFuncAttributeMaxDynamicSharedMemorySize, SM_TOT);

    // CSR build (merged scan; fill carries the layer-0 feature scatter)
    k_init<<<98, 512>>>(batch, W1, W2);
    k_deg<<<(EE + 1023) / 1024, 1024>>>(dst);
    k_blocksum<<<NBLK2, 256>>>();
    k_scanlocal<<<NBLK2, 256>>>();
    k_fill<<<(EE + 1023) / 1024, 1024>>>(src, dst, x);

    // layer 0 (xagg already aggregated by k_fill; self-loop folded into gemm0)
    k_gemm0<<<NN / 8, 256>>>(W0, b0, x);
    // layer 1
    k_tcgemm<<<MBLK, 256, SM_TOT>>>(gm0, be0, 0, 0);
    k_gather<<<NN / 8, 256>>>(b1, 1);
    // layer 2
    k_tcgemm<<<MBLK, 256, SM_TOT>>>(gm1, be1, 1, 1);
    k_gather<<<NN / 8, 256>>>(b2, 2);

    // pool + head (per-graph: 2048 blocks)
    k_poolmlp<<<GG, 128>>>(gm2, be2, fc1_w, fc1_b, fc2_w, fc2_b,
                           out_w, out_b, out);
}

// round 15
// speedup vs baseline: 1.0581x; 1.0581x over previous
#include <cuda_runtime.h>
#include <cuda_bf16.h>
#include <cuda_fp16.h>
#include <cstdint>

#define NN 50000
#define EE 600000
#define HH 128
#define GG 2048
#define NBLK2 196        // ceil(50000/256)
#define MBLK 782         // ceil(50000/64)
#define KPAD 136         // padded row length (conflict-free ldmatrix rows)

// ---------------- scratch (static device globals) ----------------
__device__ __half g_h16[NN * HH];   // GEMM output (fp16, gather operand)
__device__ float g_agg[NN * HH];    // conv output (pre-BN, fp32)
__device__ float g_xagg[NN * 9];    // aggregated raw features (layer-0 trick)
__device__ float g_dis[NN];         // deg^-1/2 (incl self loop)
__device__ int   g_deg[NN];
__device__ int   g_rowstart[NN + 1];
__device__ int   g_cursor[NN];
__device__ int2  g_edge[EE];        // (src, coef-bits) per CSR slot
__device__ int   g_partial[256];
__device__ float g_sumL[3][HH];
__device__ float g_sumsqL[3][HH];
__device__ int   g_gstart[GG], g_gend[GG];
__device__ __half g_Wimg[2][128 * KPAD];  // [layer] fp16 W^T padded [n][k]

// ---------------- fused preprocessing: zero deg/stats + W images + ranges ----------------
__global__ __launch_bounds__(512) void k_init(const int* __restrict__ batch,
                                              const float* __restrict__ W1,
                                              const float* __restrict__ W2) {
    int i = blockIdx.x * blockDim.x + threadIdx.x;   // 0 .. 50175
    if (i < NN) {
        g_deg[i] = 0;
        int b = batch[i];
        if (i == 0 || batch[i - 1] != b) g_gstart[b] = i;
        if (i == NN - 1 || batch[i + 1] != b) g_gend[b] = i + 1;
    }
    if (i < 3 * HH) { ((float*)g_sumL)[i] = 0.f; ((float*)g_sumsqL)[i] = 0.f; }
    if (i == 0) g_rowstart[NN] = EE;
    // W images: 2*128*128 = 32768 elements
    if (i < 2 * 128 * 128) {
        int mat = i >> 14;
        int rem = i & 16383;
        int n = rem >> 7;
        int k = rem & 127;
        float v = (mat ? W2 : W1)[k * 128 + n];
        g_Wimg[mat][n * KPAD + k] = __float2half_rn(v);
    }
}

__global__ void k_deg(const int* __restrict__ dst) {
    int e = blockIdx.x * blockDim.x + threadIdx.x;
    if (e < EE) atomicAdd(&g_deg[dst[e]], 1);
}

__global__ __launch_bounds__(256) void k_blocksum() {
    int t = threadIdx.x;
    int i = blockIdx.x * 256 + t;
    int v = (i < NN) ? g_deg[i] : 0;
    if (i < NN) g_dis[i] = rsqrtf((float)v + 1.0f);
    int s = v;
#pragma unroll
    for (int o = 16; o > 0; o >>= 1) s += __shfl_down_sync(0xffffffffu, s, o);
    __shared__ int ws[8];
    if ((t & 31) == 0) ws[t >> 5] = s;
    __syncthreads();
    if (t < 8) {
        int x = ws[t];
#pragma unroll
        for (int o = 4; o > 0; o >>= 1) x += __shfl_down_sync(0xffu, x, o);
        if (t == 0) g_partial[blockIdx.x] = x;
    }
}

// merged: each block scans the 196 partials itself, then does its local scan
__global__ __launch_bounds__(256) void k_scanlocal() {
    __shared__ int pp[256];
    __shared__ int blockoff;
    int t = threadIdx.x;
    int lane = t & 31, w = t >> 5;

    // phase A: scan partials to get this block's exclusive offset
    int pv = (t < NBLK2) ? g_partial[t] : 0;
    pp[t] = pv;
    __syncthreads();
    for (int o = 1; o < 256; o <<= 1) {
        int xx = (t >= o) ? pp[t - o] : 0;
        __syncthreads();
        pp[t] += xx;
        __syncthreads();
    }
    if (t == blockIdx.x) blockoff = pp[t] - pv;   // blockIdx.x < 196 < 256
    __syncthreads();

    // phase B: local exclusive scan
    int i = blockIdx.x * 256 + t;
    int v = (i < NN) ? g_deg[i] : 0;
    int x = v;
#pragma unroll
    for (int o = 1; o < 32; o <<= 1) {
        int y = __shfl_up_sync(0xffffffffu, x, o);
        if (lane >= o) x += y;
    }
    __shared__ int ws[8];
    if (lane == 31) ws[w] = x;
    __syncthreads();
    int add = blockoff;
    for (int j = 0; j < 8; j++) add += (j < w) ? ws[j] : 0;
    int excl = x - v + add;
    if (i < NN) { g_rowstart[i] = excl; g_cursor[i] = excl; }
}

__global__ void k_fill(const int* __restrict__ src, const int* __restrict__ dst) {
    int e = blockIdx.x * blockDim.x + threadIdx.x;
    if (e >= EE) return;
    int d = dst[e], s = src[e];
    int p = atomicAdd(&g_cursor[d], 1);
    float c = g_dis[s] * g_dis[d];
    g_edge[p] = make_int2(s, __float_as_int(c));
}

// ---------------- layer-0 raw-feature gather (9 channels) ----------------
__global__ __launch_bounds__(256) void k_gather9(const float* __restrict__ x) {
    int w = threadIdx.x >> 5;
    int lane = threadIdx.x & 31;
    int node = blockIdx.x * 8 + w;
    int beg = g_rowstart[node], end = g_rowstart[node + 1];
    bool act = lane < 9;
    float acc = 0.f;
    int e = beg;
    for (; e + 2 <= end; e += 2) {
        int2 e0 = g_edge[e], e1 = g_edge[e + 1];
        float c0 = __int_as_float(e0.y), c1 = __int_as_float(e1.y);
        if (act)
            acc += x[e0.x * 9 + lane] * c0 + x[e1.x * 9 + lane] * c1;
    }
    if (e < end) {
        int2 e0 = g_edge[e];
        if (act) acc += x[e0.x * 9 + lane] * __int_as_float(e0.y);
    }
    float di = g_dis[node];
    if (act) g_xagg[node * 9 + lane] = acc + x[node * 9 + lane] * di * di;
}

// ---------------- GEMM layer 0: g_agg = xagg @ W0 + b0, fused BN stats ----------------
__global__ __launch_bounds__(256) void k_gemm0(const float* __restrict__ W0,
                                               const float* __restrict__ b0) {
    __shared__ float Ws[9 * 128];
    __shared__ float sm[8][128];
    int tid = threadIdx.x;
    for (int i = tid; i < 9 * 128; i += 256) Ws[i] = W0[i];
    __syncthreads();
    int rsub = tid >> 5;       // 8 rows per block
    int c4 = tid & 31;
    int row = blockIdx.x * 8 + rsub;   // grid exactly covers NN
    float xr[9];
#pragma unroll
    for (int k = 0; k < 9; k++) xr[k] = g_xagg[row * 9 + k];
    float4 acc = ((const float4*)b0)[c4];
#pragma unroll
    for (int k = 0; k < 9; k++) {
        float4 w = *(const float4*)&Ws[k * 128 + c4 * 4];
        acc.x += xr[k] * w.x; acc.y += xr[k] * w.y;
        acc.z += xr[k] * w.z; acc.w += xr[k] * w.w;
    }
    *(float4*)&g_agg[(size_t)row * 128 + c4 * 4] = acc;

    // fused BN stats (layer-0)
    *(float4*)&sm[rsub][c4 * 4] = acc;
    __syncthreads();
    if (tid < 128) {
        float s = 0.f, q = 0.f;
#pragma unroll
        for (int j = 0; j < 8; j++) {
            float v = sm[j][tid];
            s += v;
            q += v * v;
        }
        atomicAdd(&g_sumL[0][tid], s);
        atomicAdd(&g_sumsqL[0][tid], q);
    }
}

// ---------------- GEMM layers 1,2: single-pass fp16 mma.sync + ldmatrix ----------------
#define SM_SC  0
#define SM_SH  512
#define SM_A16 1024
#define SM_B16 (1024 + 64 * KPAD * 2)
#define SM_TOT (SM_B16 + 128 * KPAD * 2)

__device__ __forceinline__ void ldm_x4(uint32_t* f, uint32_t addr) {
    asm volatile("ldmatrix.sync.aligned.m8n8.x4.shared.b16 {%0,%1,%2,%3}, [%4];"
                 : "=r"(f[0]), "=r"(f[1]), "=r"(f[2]), "=r"(f[3]) : "r"(addr));
}

__global__ __launch_bounds__(256, 2)
void k_tcgemm(const float* __restrict__ gamma, const float* __restrict__ beta,
              int sidx, int wmat) {
    extern __shared__ char smem[];
    float* sc = (float*)(smem + SM_SC);
    float* sh = (float*)(smem + SM_SH);
    __half* A16 = (__half*)(smem + SM_A16);
    __half* B16 = (__half*)(smem + SM_B16);

    int tid = threadIdx.x;
    int rbase = blockIdx.x * 64;

    if (tid < 128) {
        float m = g_sumL[sidx][tid] * (1.0f / NN);
        float v = g_sumsqL[sidx][tid] * (1.0f / NN) - m * m;
        float s = rsqrtf(v + 1e-5f) * gamma[tid];
        sc[tid] = s;
        sh[tid] = beta[tid] - m * s;
    }
    {
        const float4* bsrc = (const float4*)g_Wimg[wmat];
        float4* bd = (float4*)B16;
        for (int i = tid; i < 128 * KPAD / 8; i += 256) bd[i] = bsrc[i];
    }
    __syncthreads();

    // A tile: BN+ReLU -> fp16
#pragma unroll
    for (int it = 0; it < 8; it++) {
        int g = tid + it * 256;
        int row = g >> 5;
        int c = (g & 31) * 4;
        int grow = rbase + row;
        float4 v = {0.f, 0.f, 0.f, 0.f};
        if (grow < NN) v = *(const float4*)&g_agg[(size_t)grow * 128 + c];
        float a0 = fmaxf(v.x * sc[c + 0] + sh[c + 0], 0.f);
        float a1 = fmaxf(v.y * sc[c + 1] + sh[c + 1], 0.f);
        float a2 = fmaxf(v.z * sc[c + 2] + sh[c + 2], 0.f);
        float a3 = fmaxf(v.w * sc[c + 3] + sh[c + 3], 0.f);
        __half2* dst2 = (__half2*)&A16[row * KPAD + c];
        dst2[0] = __floats2half2_rn(a0, a1);
        dst2[1] = __floats2half2_rn(a2, a3);
    }
    __syncthreads();

    int wid = tid >> 5;
    int lane = tid & 31;
    int wm = wid & 1;
    int wn = wid >> 1;
    int quad = lane >> 3;
    int qr = lane & 7;
    int grp = lane >> 2;
    int tig = lane & 3;

    int aoff = ((quad & 1) * 8 + qr) * KPAD + (quad >> 1) * 8;
    int boff = ((quad >> 1) * 8 + qr) * KPAD + (quad & 1) * 8;

    uint32_t a_b = (uint32_t)__cvta_generic_to_shared(A16);
    uint32_t b_b = (uint32_t)__cvta_generic_to_shared(B16);

    float acc[2][4][4];
#pragma unroll
    for (int i = 0; i < 2; i++)
#pragma unroll
        for (int j = 0; j < 4; j++)
#pragma unroll
            for (int l = 0; l < 4; l++) acc[i][j][l] = 0.f;

#pragma unroll
    for (int kk = 0; kk < 8; kk++) {
        int k0 = kk * 16;
        uint32_t af[2][4], bf[2][4];
#pragma unroll
        for (int mt = 0; mt < 2; mt++)
            ldm_x4(af[mt], a_b + (uint32_t)(((wm * 32 + mt * 16) * KPAD + k0 + aoff) * 2));
#pragma unroll
        for (int g2 = 0; g2 < 2; g2++)
            ldm_x4(bf[g2], b_b + (uint32_t)(((wn * 32 + g2 * 16) * KPAD + k0 + boff) * 2));
#pragma unroll
        for (int mt = 0; mt < 2; mt++) {
#pragma unroll
            for (int nt = 0; nt < 4; nt++) {
                uint32_t b0 = bf[nt >> 1][(nt & 1) * 2];
                uint32_t b1 = bf[nt >> 1][(nt & 1) * 2 + 1];
                asm volatile(
                    "mma.sync.aligned.m16n8k16.row.col.f32.f16.f16.f32 "
                    "{%0,%1,%2,%3}, {%4,%5,%6,%7}, {%8,%9}, {%0,%1,%2,%3};"
                    : "+f"(acc[mt][nt][0]), "+f"(acc[mt][nt][1]),
                      "+f"(acc[mt][nt][2]), "+f"(acc[mt][nt][3])
                    : "r"(af[mt][0]), "r"(af[mt][1]), "r"(af[mt][2]), "r"(af[mt][3]),
                      "r"(b0), "r"(b1));
            }
        }
    }

    __half2* hv = (__half2*)g_h16;
#pragma unroll
    for (int mt = 0; mt < 2; mt++) {
        int row0 = rbase + wm * 32 + mt * 16 + grp;
        int row1 = row0 + 8;
#pragma unroll
        for (int nt = 0; nt < 4; nt++) {
            int col = wn * 32 + nt * 8 + tig * 2;
            if (row0 < NN)
                hv[row0 * 64 + (col >> 1)] = __floats2half2_rn(acc[mt][nt][0], acc[mt][nt][1]);
            if (row1 < NN)
                hv[row1 * 64 + (col >> 1)] = __floats2half2_rn(acc[mt][nt][2], acc[mt][nt][3]);
        }
    }
}

// ---------------- gather (fp16 operand, x2 unroll) + fused BN stats ----------------
__global__ __launch_bounds__(256) void k_gather(const float* __restrict__ bias, int sidx) {
    int w = threadIdx.x >> 5;
    int lane = threadIdx.x & 31;
    int node = blockIdx.x * 8 + w;
    int beg = g_rowstart[node], end = g_rowstart[node + 1];
    const uint2* hv = (const uint2*)g_h16;

    float4 a0 = {0.f, 0.f, 0.f, 0.f}, a1 = {0.f, 0.f, 0.f, 0.f};
    int e = beg;
    for (; e + 2 <= end; e += 2) {
        int2 e0 = g_edge[e], e1 = g_edge[e + 1];
        uint2 u0 = hv[(size_t)e0.x * 32 + lane];
        uint2 u1 = hv[(size_t)e1.x * 32 + lane];
        float c0 = __int_as_float(e0.y), c1 = __int_as_float(e1.y);
        float2 f00 = __half22float2(*(__half2*)&u0.x);
        float2 f01 = __half22float2(*(__half2*)&u0.y);
        float2 f10 = __half22float2(*(__half2*)&u1.x);
        float2 f11 = __half22float2(*(__half2*)&u1.y);
        a0.x += f00.x * c0; a0.y += f00.y * c0; a0.z += f01.x * c0; a0.w += f01.y * c0;
        a1.x += f10.x * c1; a1.y += f10.y * c1; a1.z += f11.x * c1; a1.w += f11.y * c1;
    }
    if (e < end) {
        int2 e0 = g_edge[e];
        uint2 u0 = hv[(size_t)e0.x * 32 + lane];
        float c0 = __int_as_float(e0.y);
        float2 f00 = __half22float2(*(__half2*)&u0.x);
        float2 f01 = __half22float2(*(__half2*)&u0.y);
        a0.x += f00.x * c0; a0.y += f00.y * c0; a0.z += f01.x * c0; a0.w += f01.y * c0;
    }
    float di = g_dis[node];
    float d2 = di * di;
    uint2 us = hv[(size_t)node * 32 + lane];
    float2 s0 = __half22float2(*(__half2*)&us.x);
    float2 s1 = __half22float2(*(__half2*)&us.y);
    float4 bb = ((const float4*)bias)[lane];
    float4 acc;
    acc.x = a0.x + a1.x + s0.x * d2 + bb.x;
    acc.y = a0.y + a1.y + s0.y * d2 + bb.y;
    acc.z = a0.z + a1.z + s1.x * d2 + bb.z;
    acc.w = a0.w + a1.w + s1.y * d2 + bb.w;
    ((float4*)g_agg)[(size_t)node * 32 + lane] = acc;

    __shared__ float sm[8][128];
    *(float4*)&sm[w][lane * 4] = acc;
    __syncthreads();
    int t = threadIdx.x;
    if (t < 128) {
        float s = 0.f, q = 0.f;
#pragma unroll
        for (int j = 0; j < 8; j++) {
            float v = sm[j][t];
            s += v;
            q += v * v;
        }
        atomicAdd(&g_sumL[sidx][t], s);
        atomicAdd(&g_sumsqL[sidx][t], q);
    }
}

// ---------------- fused pool (BN2 inline) + MLP head (per-graph, 2048 blocks) ----------------
__global__ __launch_bounds__(128) void k_poolmlp(const float* __restrict__ gamma,
                                                 const float* __restrict__ beta,
                                                 const float* __restrict__ fc1_w,
                                                 const float* __restrict__ fc1_b,
                                                 const float* __restrict__ fc2_w,
                                                 const float* __restrict__ fc2_b,
                                                 const float* __restrict__ out_w,
                                                 const float* __restrict__ out_b,
                                                 float* __restrict__ out) {
    __shared__ float zs[256];
    __shared__ float h1[128];
    __shared__ float h2[64];
    int g = blockIdx.x;
    int t = threadIdx.x;

    float m = g_sumL[2][t] * (1.0f / NN);
    float va = g_sumsqL[2][t] * (1.0f / NN) - m * m;
    float sc = rsqrtf(va + 1e-5f) * gamma[t];
    float sh = beta[t] - m * sc;

    int s = g_gstart[g], e = g_gend[g];
    float sum = 0.f, mx = -3.4e38f;
    for (int n = s; n < e; n++) {
        float v = fmaxf(g_agg[(size_t)n * 128 + t] * sc + sh, 0.f);
        sum += v;
        mx = fmaxf(mx, v);
    }
    zs[t] = sum / (float)(e - s);
    zs[128 + t] = mx;
    __syncthreads();

    float acc = fc1_b[t];
#pragma unroll 8
    for (int k = 0; k < 256; k++) acc += zs[k] * fc1_w[k * 128 + t];
    h1[t] = fmaxf(acc, 0.f);
    __syncthreads();
    if (t < 64) {
        float a = fc2_b[t];
#pragma unroll 8
        for (int k = 0; k < 128; k++) a += h1[k] * fc2_w[k * 64 + t];
        h2[t] = fmaxf(a, 0.f);
    }
    __syncthreads();
    if (t < 5) {
        float a = out_b[t];
#pragma unroll
        for (int k = 0; k < 64; k++) a += h2[k] * out_w[k * 5 + t];
        out[g * 5 + t] = a;
    }
}

// ---------------- launch ----------------
extern "C" void kernel_launch(void* const* d_in, const int* in_sizes, int n_in,
                              void* d_out, int out_size) {
    const float* x = (const float*)d_in[0];
    const int* ei = (const int*)d_in[1];
    const int* src = ei;
    const int* dst = ei + EE;
    const int* batch = (const int*)d_in[2];
    const float* W0 = (const float*)d_in[3];
    const float* b0 = (const float*)d_in[4];
    const float* gm0 = (const float*)d_in[5];
    const float* be0 = (const float*)d_in[6];
    const float* W1 = (const float*)d_in[7];
    const float* b1 = (const float*)d_in[8];
    const float* gm1 = (const float*)d_in[9];
    const float* be1 = (const float*)d_in[10];
    const float* W2 = (const float*)d_in[11];
    const float* b2 = (const float*)d_in[12];
    const float* gm2 = (const float*)d_in[13];
    const float* be2 = (const float*)d_in[14];
    const float* fc1_w = (const float*)d_in[15];
    const float* fc1_b = (const float*)d_in[16];
    const float* fc2_w = (const float*)d_in[17];
    const float* fc2_b = (const float*)d_in[18];
    const float* out_w = (const float*)d_in[19];
    const float* out_b = (const float*)d_in[20];
    float* out = (float*)d_out;

    cudaFuncSetAttribute(k_tcgemm, cudaFuncAttributeMaxDynamicSharedMemorySize, SM_TOT);

    // CSR build (merged scan)
    k_init<<<98, 512>>>(batch, W1, W2);
    k_deg<<<(EE + 1023) / 1024, 1024>>>(dst);
    k_blocksum<<<NBLK2, 256>>>();
    k_scanlocal<<<NBLK2, 256>>>();
    k_fill<<<(EE + 1023) / 1024, 1024>>>(src, dst);

    // layer 0 (linearity trick: aggregate 9-ch x via CSR gather, then W0+b0)
    k_gather9<<<NN / 8, 256>>>(x);
    k_gemm0<<<NN / 8, 256>>>(W0, b0);
    // layer 1
    k_tcgemm<<<MBLK, 256, SM_TOT>>>(gm0, be0, 0, 0);
    k_gather<<<NN / 8, 256>>>(b1, 1);
    // layer 2
    k_tcgemm<<<MBLK, 256, SM_TOT>>>(gm1, be1, 1, 1);
    k_gather<<<NN / 8, 256>>>(b2, 2);

    // pool + head (per-graph: 2048 blocks)
    k_poolmlp<<<GG, 128>>>(gm2, be2, fc1_w, fc1_b, fc2_w, fc2_b,
                           out_w, out_b, out);
}

// round 16
// speedup vs baseline: 1.1548x; 1.0914x over previous
#include <cuda_runtime.h>
#include <cuda_bf16.h>
#include <cuda_fp16.h>
#include <cstdint>

#define NN 50000
#define EE 600000
#define HH 128
#define GG 2048
#define NBLK2 196        // ceil(50000/256)
#define MBLK 782         // ceil(50000/64)
#define KPAD 136         // padded row length (conflict-free ldmatrix rows)

// ---------------- scratch (static device globals) ----------------
__device__ __half g_h16[NN * HH];   // GEMM output (fp16, gather operand)
__device__ float g_agg[NN * HH];    // conv output (pre-BN, fp32)
__device__ float g_dis[NN];         // deg^-1/2 (incl self loop)
__device__ int   g_deg[NN];         // zero at load; self-reset by k_scanlocal each run
__device__ int   g_rowstart[NN + 1];
__device__ int   g_cursor[NN];
__device__ int2  g_edge[EE];        // (src, coef-bits) per CSR slot
__device__ int   g_partial[256];
__device__ float g_sumL[3][HH];
__device__ float g_sumsqL[3][HH];
__device__ int   g_gstart[GG], g_gend[GG];
__device__ __half g_Wimg[2][128 * KPAD];  // [layer] fp16 W^T padded [n][k]

// ---------------- degree count + fused glue init (ranges, stats, W images) ----------------
// g_deg is NOT zeroed here: zero at module load, then reset by k_scanlocal each run.
__global__ __launch_bounds__(512) void k_deg(const int* __restrict__ dst,
                                             const int* __restrict__ batch,
                                             const float* __restrict__ W1,
                                             const float* __restrict__ W2) {
    int i = blockIdx.x * blockDim.x + threadIdx.x;
    if (i < EE) atomicAdd(&g_deg[dst[i]], 1);
    if (i < NN) {
        int b = batch[i];
        if (i == 0 || batch[i - 1] != b) g_gstart[b] = i;
        if (i == NN - 1 || batch[i + 1] != b) g_gend[b] = i + 1;
    }
    if (i < 3 * HH) { ((float*)g_sumL)[i] = 0.f; ((float*)g_sumsqL)[i] = 0.f; }
    if (i == 0) g_rowstart[NN] = EE;
    if (i < 2 * 128 * 128) {
        int mat = i >> 14;
        int rem = i & 16383;
        int n = rem >> 7;
        int k = rem & 127;
        float v = (mat ? W2 : W1)[k * 128 + n];
        g_Wimg[mat][n * KPAD + k] = __float2half_rn(v);
    }
}

__global__ __launch_bounds__(256) void k_blocksum() {
    int t = threadIdx.x;
    int i = blockIdx.x * 256 + t;
    int v = (i < NN) ? g_deg[i] : 0;
    if (i < NN) g_dis[i] = rsqrtf((float)v + 1.0f);
    int s = v;
#pragma unroll
    for (int o = 16; o > 0; o >>= 1) s += __shfl_down_sync(0xffffffffu, s, o);
    __shared__ int ws[8];
    if ((t & 31) == 0) ws[t >> 5] = s;
    __syncthreads();
    if (t < 8) {
        int x = ws[t];
#pragma unroll
        for (int o = 4; o > 0; o >>= 1) x += __shfl_down_sync(0xffu, x, o);
        if (t == 0) g_partial[blockIdx.x] = x;
    }
}

// merged: each block scans the 196 partials itself, then does its local scan.
// Also RESETS g_deg to 0 for the next graph replay (last reader of g_deg).
__global__ __launch_bounds__(256) void k_scanlocal() {
    __shared__ int pp[256];
    __shared__ int blockoff;
    int t = threadIdx.x;
    int lane = t & 31, w = t >> 5;

    int pv = (t < NBLK2) ? g_partial[t] : 0;
    pp[t] = pv;
    __syncthreads();
    for (int o = 1; o < 256; o <<= 1) {
        int xx = (t >= o) ? pp[t - o] : 0;
        __syncthreads();
        pp[t] += xx;
        __syncthreads();
    }
    if (t == blockIdx.x) blockoff = pp[t] - pv;
    __syncthreads();

    int i = blockIdx.x * 256 + t;
    int v = 0;
    if (i < NN) {
        v = g_deg[i];
        g_deg[i] = 0;          // self-reset for next replay
    }
    int x = v;
#pragma unroll
    for (int o = 1; o < 32; o <<= 1) {
        int y = __shfl_up_sync(0xffffffffu, x, o);
        if (lane >= o) x += y;
    }
    __shared__ int ws[8];
    if (lane == 31) ws[w] = x;
    __syncthreads();
    int add = blockoff;
    for (int j = 0; j < 8; j++) add += (j < w) ? ws[j] : 0;
    int excl = x - v + add;
    if (i < NN) { g_rowstart[i] = excl; g_cursor[i] = excl; }
}

__global__ void k_fill(const int* __restrict__ src, const int* __restrict__ dst) {
    int e = blockIdx.x * blockDim.x + threadIdx.x;
    if (e >= EE) return;
    int d = dst[e], s = src[e];
    int p = atomicAdd(&g_cursor[d], 1);
    float c = g_dis[s] * g_dis[d];
    g_edge[p] = make_int2(s, __float_as_int(c));
}

// ---------------- layer 0 fused: 9-ch CSR gather (smem) -> @W0+b0 -> BN stats ----------------
__global__ __launch_bounds__(256) void k_layer0(const float* __restrict__ x,
                                                const float* __restrict__ W0,
                                                const float* __restrict__ b0) {
    __shared__ float Ws[9 * 128];
    __shared__ float xs[8][12];    // 9 used, padded
    __shared__ float sm[8][128];
    int tid = threadIdx.x;
    for (int i = tid; i < 9 * 128; i += 256) Ws[i] = W0[i];

    int w = tid >> 5;
    int lane = tid & 31;
    int node = blockIdx.x * 8 + w;
    int beg = g_rowstart[node], end = g_rowstart[node + 1];
    bool act = lane < 9;
    float acc = 0.f;
    int e = beg;
    for (; e + 2 <= end; e += 2) {
        int2 e0 = g_edge[e], e1 = g_edge[e + 1];
        float c0 = __int_as_float(e0.y), c1 = __int_as_float(e1.y);
        if (act)
            acc += x[e0.x * 9 + lane] * c0 + x[e1.x * 9 + lane] * c1;
    }
    if (e < end) {
        int2 e0 = g_edge[e];
        if (act) acc += x[e0.x * 9 + lane] * __int_as_float(e0.y);
    }
    float di = g_dis[node];
    if (act) xs[w][lane] = acc + x[node * 9 + lane] * di * di;
    __syncthreads();

    // GEMM part: thread (rsub, c4) computes 4 outputs of row rsub
    int rsub = w;
    int c4 = lane;
    int row = node;   // = blockIdx.x * 8 + rsub
    float xr[9];
#pragma unroll
    for (int k = 0; k < 9; k++) xr[k] = xs[rsub][k];
    float4 a = ((const float4*)b0)[c4];
#pragma unroll
    for (int k = 0; k < 9; k++) {
        float4 wv = *(const float4*)&Ws[k * 128 + c4 * 4];
        a.x += xr[k] * wv.x; a.y += xr[k] * wv.y;
        a.z += xr[k] * wv.z; a.w += xr[k] * wv.w;
    }
    *(float4*)&g_agg[(size_t)row * 128 + c4 * 4] = a;

    // fused BN stats (layer-0)
    *(float4*)&sm[rsub][c4 * 4] = a;
    __syncthreads();
    if (tid < 128) {
        float s = 0.f, q = 0.f;
#pragma unroll
        for (int j = 0; j < 8; j++) {
            float v = sm[j][tid];
            s += v;
            q += v * v;
        }
        atomicAdd(&g_sumL[0][tid], s);
        atomicAdd(&g_sumsqL[0][tid], q);
    }
}

// ---------------- GEMM layers 1,2: single-pass fp16 mma.sync + ldmatrix ----------------
#define SM_SC  0
#define SM_SH  512
#define SM_A16 1024
#define SM_B16 (1024 + 64 * KPAD * 2)
#define SM_TOT (SM_B16 + 128 * KPAD * 2)

__device__ __forceinline__ void ldm_x4(uint32_t* f, uint32_t addr) {
    asm volatile("ldmatrix.sync.aligned.m8n8.x4.shared.b16 {%0,%1,%2,%3}, [%4];"
                 : "=r"(f[0]), "=r"(f[1]), "=r"(f[2]), "=r"(f[3]) : "r"(addr));
}

__global__ __launch_bounds__(256, 2)
void k_tcgemm(const float* __restrict__ gamma, const float* __restrict__ beta,
              int sidx, int wmat) {
    extern __shared__ char smem[];
    float* sc = (float*)(smem + SM_SC);
    float* sh = (float*)(smem + SM_SH);
    __half* A16 = (__half*)(smem + SM_A16);
    __half* B16 = (__half*)(smem + SM_B16);

    int tid = threadIdx.x;
    int rbase = blockIdx.x * 64;

    if (tid < 128) {
        float m = g_sumL[sidx][tid] * (1.0f / NN);
        float v = g_sumsqL[sidx][tid] * (1.0f / NN) - m * m;
        float s = rsqrtf(v + 1e-5f) * gamma[tid];
        sc[tid] = s;
        sh[tid] = beta[tid] - m * s;
    }
    {
        const float4* bsrc = (const float4*)g_Wimg[wmat];
        float4* bd = (float4*)B16;
        for (int i = tid; i < 128 * KPAD / 8; i += 256) bd[i] = bsrc[i];
    }
    __syncthreads();

    // A tile: BN+ReLU -> fp16
#pragma unroll
    for (int it = 0; it < 8; it++) {
        int g = tid + it * 256;
        int row = g >> 5;
        int c = (g & 31) * 4;
        int grow = rbase + row;
        float4 v = {0.f, 0.f, 0.f, 0.f};
        if (grow < NN) v = *(const float4*)&g_agg[(size_t)grow * 128 + c];
        float a0 = fmaxf(v.x * sc[c + 0] + sh[c + 0], 0.f);
        float a1 = fmaxf(v.y * sc[c + 1] + sh[c + 1], 0.f);
        float a2 = fmaxf(v.z * sc[c + 2] + sh[c + 2], 0.f);
        float a3 = fmaxf(v.w * sc[c + 3] + sh[c + 3], 0.f);
        __half2* dst2 = (__half2*)&A16[row * KPAD + c];
        dst2[0] = __floats2half2_rn(a0, a1);
        dst2[1] = __floats2half2_rn(a2, a3);
    }
    __syncthreads();

    int wid = tid >> 5;
    int lane = tid & 31;
    int wm = wid & 1;
    int wn = wid >> 1;
    int quad = lane >> 3;
    int qr = lane & 7;
    int grp = lane >> 2;
    int tig = lane & 3;

    int aoff = ((quad & 1) * 8 + qr) * KPAD + (quad >> 1) * 8;
    int boff = ((quad >> 1) * 8 + qr) * KPAD + (quad & 1) * 8;

    uint32_t a_b = (uint32_t)__cvta_generic_to_shared(A16);
    uint32_t b_b = (uint32_t)__cvta_generic_to_shared(B16);

    float acc[2][4][4];
#pragma unroll
    for (int i = 0; i < 2; i++)
#pragma unroll
        for (int j = 0; j < 4; j++)
#pragma unroll
            for (int l = 0; l < 4; l++) acc[i][j][l] = 0.f;

#pragma unroll
    for (int kk = 0; kk < 8; kk++) {
        int k0 = kk * 16;
        uint32_t af[2][4], bf[2][4];
#pragma unroll
        for (int mt = 0; mt < 2; mt++)
            ldm_x4(af[mt], a_b + (uint32_t)(((wm * 32 + mt * 16) * KPAD + k0 + aoff) * 2));
#pragma unroll
        for (int g2 = 0; g2 < 2; g2++)
            ldm_x4(bf[g2], b_b + (uint32_t)(((wn * 32 + g2 * 16) * KPAD + k0 + boff) * 2));
#pragma unroll
        for (int mt = 0; mt < 2; mt++) {
#pragma unroll
            for (int nt = 0; nt < 4; nt++) {
                uint32_t b0 = bf[nt >> 1][(nt & 1) * 2];
                uint32_t b1 = bf[nt >> 1][(nt & 1) * 2 + 1];
                asm volatile(
                    "mma.sync.aligned.m16n8k16.row.col.f32.f16.f16.f32 "
                    "{%0,%1,%2,%3}, {%4,%5,%6,%7}, {%8,%9}, {%0,%1,%2,%3};"
                    : "+f"(acc[mt][nt][0]), "+f"(acc[mt][nt][1]),
                      "+f"(acc[mt][nt][2]), "+f"(acc[mt][nt][3])
                    : "r"(af[mt][0]), "r"(af[mt][1]), "r"(af[mt][2]), "r"(af[mt][3]),
                      "r"(b0), "r"(b1));
            }
        }
    }

    __half2* hv = (__half2*)g_h16;
#pragma unroll
    for (int mt = 0; mt < 2; mt++) {
        int row0 = rbase + wm * 32 + mt * 16 + grp;
        int row1 = row0 + 8;
#pragma unroll
        for (int nt = 0; nt < 4; nt++) {
            int col = wn * 32 + nt * 8 + tig * 2;
            if (row0 < NN)
                hv[row0 * 64 + (col >> 1)] = __floats2half2_rn(acc[mt][nt][0], acc[mt][nt][1]);
            if (row1 < NN)
                hv[row1 * 64 + (col >> 1)] = __floats2half2_rn(acc[mt][nt][2], acc[mt][nt][3]);
        }
    }
}

// ---------------- gather (fp16 operand, x2 unroll) + fused BN stats ----------------
__global__ __launch_bounds__(256) void k_gather(const float* __restrict__ bias, int sidx) {
    int w = threadIdx.x >> 5;
    int lane = threadIdx.x & 31;
    int node = blockIdx.x * 8 + w;
    int beg = g_rowstart[node], end = g_rowstart[node + 1];
    const uint2* hv = (const uint2*)g_h16;

    float4 a0 = {0.f, 0.f, 0.f, 0.f}, a1 = {0.f, 0.f, 0.f, 0.f};
    int e = beg;
    for (; e + 2 <= end; e += 2) {
        int2 e0 = g_edge[e], e1 = g_edge[e + 1];
        uint2 u0 = hv[(size_t)e0.x * 32 + lane];
        uint2 u1 = hv[(size_t)e1.x * 32 + lane];
        float c0 = __int_as_float(e0.y), c1 = __int_as_float(e1.y);
        float2 f00 = __half22float2(*(__half2*)&u0.x);
        float2 f01 = __half22float2(*(__half2*)&u0.y);
        float2 f10 = __half22float2(*(__half2*)&u1.x);
        float2 f11 = __half22float2(*(__half2*)&u1.y);
        a0.x += f00.x * c0; a0.y += f00.y * c0; a0.z += f01.x * c0; a0.w += f01.y * c0;
        a1.x += f10.x * c1; a1.y += f10.y * c1; a1.z += f11.x * c1; a1.w += f11.y * c1;
    }
    if (e < end) {
        int2 e0 = g_edge[e];
        uint2 u0 = hv[(size_t)e0.x * 32 + lane];
        float c0 = __int_as_float(e0.y);
        float2 f00 = __half22float2(*(__half2*)&u0.x);
        float2 f01 = __half22float2(*(__half2*)&u0.y);
        a0.x += f00.x * c0; a0.y += f00.y * c0; a0.z += f01.x * c0; a0.w += f01.y * c0;
    }
    float di = g_dis[node];
    float d2 = di * di;
    uint2 us = hv[(size_t)node * 32 + lane];
    float2 s0 = __half22float2(*(__half2*)&us.x);
    float2 s1 = __half22float2(*(__half2*)&us.y);
    float4 bb = ((const float4*)bias)[lane];
    float4 acc;
    acc.x = a0.x + a1.x + s0.x * d2 + bb.x;
    acc.y = a0.y + a1.y + s0.y * d2 + bb.y;
    acc.z = a0.z + a1.z + s1.x * d2 + bb.z;
    acc.w = a0.w + a1.w + s1.y * d2 + bb.w;
    ((float4*)g_agg)[(size_t)node * 32 + lane] = acc;

    __shared__ float sm[8][128];
    *(float4*)&sm[w][lane * 4] = acc;
    __syncthreads();
    int t = threadIdx.x;
    if (t < 128) {
        float s = 0.f, q = 0.f;
#pragma unroll
        for (int j = 0; j < 8; j++) {
            float v = sm[j][t];
            s += v;
            q += v * v;
        }
        atomicAdd(&g_sumL[sidx][t], s);
        atomicAdd(&g_sumsqL[sidx][t], q);
    }
}

// ---------------- fused pool (BN2 inline) + MLP head (per-graph, 2048 blocks) ----------------
__global__ __launch_bounds__(128) void k_poolmlp(const float* __restrict__ gamma,
                                                 const float* __restrict__ beta,
                                                 const float* __restrict__ fc1_w,
                                                 const float* __restrict__ fc1_b,
                                                 const float* __restrict__ fc2_w,
                                                 const float* __restrict__ fc2_b,
                                                 const float* __restrict__ out_w,
                                                 const float* __restrict__ out_b,
                                                 float* __restrict__ out) {
    __shared__ float zs[256];
    __shared__ float h1[128];
    __shared__ float h2[64];
    int g = blockIdx.x;
    int t = threadIdx.x;

    float m = g_sumL[2][t] * (1.0f / NN);
    float va = g_sumsqL[2][t] * (1.0f / NN) - m * m;
    float sc = rsqrtf(va + 1e-5f) * gamma[t];
    float sh = beta[t] - m * sc;

    int s = g_gstart[g], e = g_gend[g];
    float sum = 0.f, mx = -3.4e38f;
    for (int n = s; n < e; n++) {
        float v = fmaxf(g_agg[(size_t)n * 128 + t] * sc + sh, 0.f);
        sum += v;
        mx = fmaxf(mx, v);
    }
    zs[t] = sum / (float)(e - s);
    zs[128 + t] = mx;
    __syncthreads();

    float acc = fc1_b[t];
#pragma unroll 8
    for (int k = 0; k < 256; k++) acc += zs[k] * fc1_w[k * 128 + t];
    h1[t] = fmaxf(acc, 0.f);
    __syncthreads();
    if (t < 64) {
        float a = fc2_b[t];
#pragma unroll 8
        for (int k = 0; k < 128; k++) a += h1[k] * fc2_w[k * 64 + t];
        h2[t] = fmaxf(a, 0.f);
    }
    __syncthreads();
    if (t < 5) {
        float a = out_b[t];
#pragma unroll
        for (int k = 0; k < 64; k++) a += h2[k] * out_w[k * 5 + t];
        out[g * 5 + t] = a;
    }
}

// ---------------- launch ----------------
extern "C" void kernel_launch(void* const* d_in, const int* in_sizes, int n_in,
                              void* d_out, int out_size) {
    const float* x = (const float*)d_in[0];
    const int* ei = (const int*)d_in[1];
    const int* src = ei;
    const int* dst = ei + EE;
    const int* batch = (const int*)d_in[2];
    const float* W0 = (const float*)d_in[3];
    const float* b0 = (const float*)d_in[4];
    const float* gm0 = (const float*)d_in[5];
    const float* be0 = (const float*)d_in[6];
    const float* W1 = (const float*)d_in[7];
    const float* b1 = (const float*)d_in[8];
    const float* gm1 = (const float*)d_in[9];
    const float* be1 = (const float*)d_in[10];
    const float* W2 = (const float*)d_in[11];
    const float* b2 = (const float*)d_in[12];
    const float* gm2 = (const float*)d_in[13];
    const float* be2 = (const float*)d_in[14];
    const float* fc1_w = (const float*)d_in[15];
    const float* fc1_b = (const float*)d_in[16];
    const float* fc2_w = (const float*)d_in[17];
    const float* fc2_b = (const float*)d_in[18];
    const float* out_w = (const float*)d_in[19];
    const float* out_b = (const float*)d_in[20];
    float* out = (float*)d_out;

    cudaFuncSetAttribute(k_tcgemm, cudaFuncAttributeMaxDynamicSharedMemorySize, SM_TOT);

    // CSR build (deg carries glue init; scanlocal self-resets g_deg for next replay)
    k_deg<<<(EE + 511) / 512, 512>>>(dst, batch, W1, W2);
    k_blocksum<<<NBLK2, 256>>>();
    k_scanlocal<<<NBLK2, 256>>>();
    k_fill<<<(EE + 1023) / 1024, 1024>>>(src, dst);

    // layer 0 (fused: 9-ch gather through smem -> @W0+b0 -> BN stats)
    k_layer0<<<NN / 8, 256>>>(x, W0, b0);
    // layer 1
    k_tcgemm<<<MBLK, 256, SM_TOT>>>(gm0, be0, 0, 0);
    k_gather<<<NN / 8, 256>>>(b1, 1);
    // layer 2
    k_tcgemm<<<MBLK, 256, SM_TOT>>>(gm1, be1, 1, 1);
    k_gather<<<NN / 8, 256>>>(b2, 2);

    // pool + head (per-graph: 2048 blocks)
    k_poolmlp<<<GG, 128>>>(gm2, be2, fc1_w, fc1_b, fc2_w, fc2_b,
                           out_w, out_b, out);
}